// round 16
// baseline (speedup 1.0000x reference)
#include <cuda_runtime.h>
#include <cuda_bf16.h>
#include <cstdint>

// TELIF: temporal-encoded LIF neuron scan — single kernel, no block barriers.
//   tx : [T, B, N] float32   (T=512, B=64, N=1024)
//   TE : [N, T]    float32
//   out: [T, B, N] float32 spikes
//
// Per (b, n), sequential in t:
//   th = th + v*TE[n,t] - (th - THRESHOLD)*BETA
//   v  = v*DECAY*(1 - y) + x
//   y  = (v > th) ? 1 : 0
//
// Warp-local cp.async pipelines for both streams (each warp copies exactly
// the floats its own lanes consume; completion = wait_group + __syncwarp,
// no __syncthreads anywhere).
//  - tx: DEPTH-12 ring of 4-timestep chunks, prefetch distance 8 chunks
//    (max compatible with TE riding the same commit-group FIFO). Since
//    lcm(8,12)=24, a 24-chunk unrolled mega-iteration makes every ring slot
//    a compile-time constant.
//  - TE: double-buffered 32-timestep x 64-row tiles from native [N,T]
//    (row = 128B -> 4 full lines per warp-op, L2-resident). Tile T+1 rides
//    the commit group of tx chunk 8T (8-chunk lead, first use 8T+8).
// BLK=64 -> grid 1024 (per-SM 7 vs mean 6.92, ~99% wave efficiency);
// smem 30KB -> 7 CTAs/SM capacity, single wave.

#define T_STEPS 512
#define B_DIM   64
#define N_DIM   1024
#define BN      (B_DIM * N_DIM)      // 65536
#define U       4                    // timesteps per chunk
#define NCHUNK  (T_STEPS / U)        // 128
#define BLK     64
#define DEPTH   12                   // tx ring depth (chunks), d=8 distance
#define TS_TILE 32                   // timesteps per TE tile (= 8 chunks)
#define TEPAD   36                   // floats per TE smem row (conflict-free)

#define REST      0.0f
#define DECAY     0.2f
#define THRESHOLD 0.3f
#define BETA      0.02f

// ---------------------------------------------------------------------------
__device__ __forceinline__ void cp_async16(uint32_t dst, const void* src) {
    asm volatile("cp.async.cg.shared.global [%0], [%1], 16;"
                 :: "r"(dst), "l"(src));
}
#define CP_COMMIT()  asm volatile("cp.async.commit_group;" ::: "memory")
#define CP_WAIT(nn)  asm volatile("cp.async.wait_group " #nn ";" ::: "memory")
#define ARRIVE(nn)   { CP_WAIT(nn); __syncwarp(); }

// ---- TE tile T -> smem buffer T&1 (8 warp-local ops; NO commit: rides in
//      the next TX_ASYNC's group). Warp w copies rows w*32..w*32+31. --------
#define TE_ASYNC(T)                                                          \
    {                                                                        \
        const int bb = (T) & 1;                                              \
        _Pragma("unroll")                                                    \
        for (int j = 0; j < 8; j++) {                                        \
            const int rt = w * 32 + j * 4 + (lane >> 3);                     \
            cp_async16(smem_te +                                             \
                           (uint32_t)(((bb * BLK + rt) * TEPAD               \
                                       + (lane & 7) * 4) * 4u),              \
                       TE + (size_t)(n0 + rt) * T_STEPS + (T) * TS_TILE      \
                          + (lane & 7) * 4);                                 \
        }                                                                    \
    }

// ---- tx chunk c -> ring slot s (compile-time) + commit --------------------
#define TX_ASYNC(c, s)                                                       \
    {                                                                        \
        cp_async16(smem_tx +                                                 \
                       (uint32_t)((((s) * U + row_) * BLK + seg_) * 4u),     \
                   tx + (size_t)((c) * U + row_) * BN + gseg_);              \
        CP_COMMIT();                                                         \
    }

// ---- one chunk of the recurrence (math form measured rel_err == 0.0) ------
#define COMPUTE_CHUNK(c, s)                                                  \
    {                                                                        \
        const float4 t4 = *reinterpret_cast<const float4*>(                  \
            &s_te[((c) >> 3) & 1][threadIdx.x][((c) & 7) * 4]);              \
        _Pragma("unroll")                                                    \
        for (int u = 0; u < U; u++) {                                        \
            const float x  = s_tx[(s)][u][threadIdx.x];                      \
            const float te = (u == 0) ? t4.x : (u == 1) ? t4.y               \
                           : (u == 2) ? t4.z : t4.w;                         \
            th = th + v * te - (th - THRESHOLD) * BETA;                      \
            const float vd = v * DECAY + x;                                  \
            v  = (y != 0.0f) ? x : vd;                                       \
            y  = (v > th) ? 1.0f : 0.0f;                                     \
            __stcs(&ty[((c) * U + u) * BN + g], y);                          \
        }                                                                    \
    }

// ---- 8 chunks at distance 8; S = slot of chunk c0 (literal) ---------------
#define GROUP8(c0, S)                                                        \
    TX_ASYNC((c0) + 8,  ((S) + 8)  % DEPTH) ARRIVE(8)                        \
        COMPUTE_CHUNK((c0) + 0, ((S) + 0) % DEPTH)                           \
    TX_ASYNC((c0) + 9,  ((S) + 9)  % DEPTH) ARRIVE(8)                        \
        COMPUTE_CHUNK((c0) + 1, ((S) + 1) % DEPTH)                           \
    TX_ASYNC((c0) + 10, ((S) + 10) % DEPTH) ARRIVE(8)                        \
        COMPUTE_CHUNK((c0) + 2, ((S) + 2) % DEPTH)                           \
    TX_ASYNC((c0) + 11, ((S) + 11) % DEPTH) ARRIVE(8)                        \
        COMPUTE_CHUNK((c0) + 3, ((S) + 3) % DEPTH)                           \
    TX_ASYNC((c0) + 12, ((S) + 12) % DEPTH) ARRIVE(8)                        \
        COMPUTE_CHUNK((c0) + 4, ((S) + 4) % DEPTH)                           \
    TX_ASYNC((c0) + 13, ((S) + 13) % DEPTH) ARRIVE(8)                        \
        COMPUTE_CHUNK((c0) + 5, ((S) + 5) % DEPTH)                           \
    TX_ASYNC((c0) + 14, ((S) + 14) % DEPTH) ARRIVE(8)                        \
        COMPUTE_CHUNK((c0) + 6, ((S) + 6) % DEPTH)                           \
    TX_ASYNC((c0) + 15, ((S) + 15) % DEPTH) ARRIVE(8)                        \
        COMPUTE_CHUNK((c0) + 7, ((S) + 7) % DEPTH)

__global__ void __launch_bounds__(BLK) telif_kernel(
    const float* __restrict__ tx,
    const float* __restrict__ TE,
    float* __restrict__ ty)
{
    __shared__ float s_tx[DEPTH][U][BLK];     // 12 KB tx ring
    __shared__ float s_te[2][BLK][TEPAD];     // 18 KB TE double buffer

    const int g    = blockIdx.x * BLK + threadIdx.x;        // g = b*N + n
    const int n0   = (blockIdx.x & (N_DIM / BLK - 1)) * BLK;
    const int lane = threadIdx.x & 31;
    const int w    = threadIdx.x >> 5;

    // tx copy mapping (constant per thread)
    const int row_  = lane >> 3;                 // timestep within chunk
    const int seg_  = w * 32 + (lane & 7) * 4;   // float index within row
    const int gseg_ = blockIdx.x * BLK + seg_;
    const uint32_t smem_tx = (uint32_t)__cvta_generic_to_shared(s_tx);
    const uint32_t smem_te = (uint32_t)__cvta_generic_to_shared(s_te);

    float v  = REST;
    float y  = 0.0f;
    float th = THRESHOLD;

    // prologue: TE tile 0 rides tx chunk 0's group; 8 tx chunks in flight
    TE_ASYNC(0)
    TX_ASYNC(0, 0) TX_ASYNC(1, 1) TX_ASYNC(2, 2) TX_ASYNC(3, 3)
    TX_ASYNC(4, 4) TX_ASYNC(5, 5) TX_ASYNC(6, 6) TX_ASYNC(7, 7)

    // steady state: 24 chunks per mega-iteration (lcm(8, DEPTH) = 24, so
    // every ring slot below is a compile-time constant). Computes chunks
    // 0..119, issues tx 8..127, TE tiles 1..15 (tile t rides tx chunk 8t-8,
    // lead 8 chunk-periods; buffer-safe: issued after last read of tile t-2).
    #pragma unroll 1
    for (int c = 0; c < NCHUNK - 8; c += 24) {
        const int t3 = c >> 3;
        TE_ASYNC(t3 + 1) GROUP8(c,      0)
        TE_ASYNC(t3 + 2) GROUP8(c + 8,  8)
        TE_ASYNC(t3 + 3) GROUP8(c + 16, 16)
    }

    // drain: chunks 120..127 (slots 0..7; TE tile 15 landed with group 120)
    ARRIVE(7) COMPUTE_CHUNK(120, 0)
    ARRIVE(6) COMPUTE_CHUNK(121, 1)
    ARRIVE(5) COMPUTE_CHUNK(122, 2)
    ARRIVE(4) COMPUTE_CHUNK(123, 3)
    ARRIVE(3) COMPUTE_CHUNK(124, 4)
    ARRIVE(2) COMPUTE_CHUNK(125, 5)
    ARRIVE(1) COMPUTE_CHUNK(126, 6)
    ARRIVE(0) COMPUTE_CHUNK(127, 7)
}

// ---------------------------------------------------------------------------
extern "C" void kernel_launch(void* const* d_in, const int* in_sizes, int n_in,
                              void* d_out, int out_size) {
    const float* tx = (const float*)d_in[0];   // [T, B, N]
    const float* TE = (const float*)d_in[1];   // [N, T]
    float* ty = (float*)d_out;                 // [T, B, N]
    (void)in_sizes; (void)n_in; (void)out_size;

    telif_kernel<<<BN / BLK, BLK>>>(tx, TE, ty);
}